// round 2
// baseline (speedup 1.0000x reference)
#include <cuda_runtime.h>

#define B_      256
#define SEQ_    128
#define HID_    1024
#define NB_     256
#define NL_     3
#define KW_     8              // k-values per CTA (one per warp) in pass 1
#define CHUNKS_ 16             // b-chunks (split softmax)
#define BPC_    (B_/CHUNKS_)   // 16 b per chunk

// Scratch (static device arrays only — no cudaMalloc allowed)
__device__ float g_part_u[NB_][CHUNKS_][HID_];   // 16 MB
__device__ float g_part_m[NB_][CHUNKS_];
__device__ float g_part_z[NB_][CHUNKS_];
__device__ float g_u[NB_][HID_];                 // 1 MB
__device__ float g_RH[NL_][HID_];                // R_w @ H_w  (3 x 1024)
__device__ float g_act[B_][HID_];                // slow-path activations
__device__ int   g_flag;                         // 1 iff alpha == 1 everywhere

// ---------------------------------------------------------------------------
// K1 (barrier-free): one WARP per (k, chunk). Lane owns h = j*128 + lane*4,
// j=0..7 (8 float4s). Score dot reduces with 5 shfl_xor; online softmax state
// (acc[8], m, z) lives in registers. Next b's S row is double-buffered.
// Grid (NB_/KW_, CHUNKS_) = (32,16), 256 threads (8 warps = 8 k's).
// All warps in a CTA share the same x row per b -> L1 broadcast.
// ---------------------------------------------------------------------------
__global__ __launch_bounds__(256, 2) void k1_partials(
    const float* __restrict__ ee, const float* __restrict__ S)
{
    const int w    = threadIdx.x >> 5;
    const int lane = threadIdx.x & 31;
    const int k    = blockIdx.x * KW_ + w;
    const int c    = blockIdx.y;
    const int b0   = c * BPC_;
    const int hoff = lane * 4;

    float4 acc[8];
    float m = -3.0e38f, z = 0.f;
#pragma unroll
    for (int j = 0; j < 8; j++) acc[j] = make_float4(0.f, 0.f, 0.f, 0.f);

    // prime: S row for b0 (row = S + (b*NB + k)*HID)
    float4 sv[8];
    {
        const float* Sb = S + ((size_t)b0 * NB_ + k) * HID_;
#pragma unroll
        for (int j = 0; j < 8; j++)
            sv[j] = *(const float4*)(Sb + j * 128 + hoff);
    }

    for (int bi = 0; bi < BPC_; bi++) {
        const int b = b0 + bi;

        // prefetch next b's S row first (keeps DRAM busy during reduce)
        float4 sn[8];
        if (bi + 1 < BPC_) {
            const float* Sn = S + ((size_t)(b + 1) * NB_ + k) * HID_;
#pragma unroll
            for (int j = 0; j < 8; j++)
                sn[j] = *(const float4*)(Sn + j * 128 + hoff);
        } else {
#pragma unroll
            for (int j = 0; j < 8; j++) sn[j] = make_float4(0.f, 0.f, 0.f, 0.f);
        }

        // partial dot x[b] . S[b,k]
        const float* xr = ee + (size_t)b * SEQ_ * HID_;
        float d = 0.f;
#pragma unroll
        for (int j = 0; j < 8; j++) {
            const float4 xv = *(const float4*)(xr + j * 128 + hoff);
            d += xv.x * sv[j].x + xv.y * sv[j].y + xv.z * sv[j].z + xv.w * sv[j].w;
        }
#pragma unroll
        for (int off = 16; off > 0; off >>= 1)
            d += __shfl_xor_sync(0xffffffffu, d, off);

        // online softmax update (branch is warp-uniform)
        if (d > m) {
            const float cf = __expf(m - d);          // first iter: exp(-huge)=0
            z = z * cf + 1.f;
#pragma unroll
            for (int j = 0; j < 8; j++) {
                acc[j].x = acc[j].x * cf + sv[j].x;
                acc[j].y = acc[j].y * cf + sv[j].y;
                acc[j].z = acc[j].z * cf + sv[j].z;
                acc[j].w = acc[j].w * cf + sv[j].w;
            }
            m = d;
        } else {
            const float wgt = __expf(d - m);
            z += wgt;
#pragma unroll
            for (int j = 0; j < 8; j++) {
                acc[j].x += wgt * sv[j].x;
                acc[j].y += wgt * sv[j].y;
                acc[j].z += wgt * sv[j].z;
                acc[j].w += wgt * sv[j].w;
            }
        }
#pragma unroll
        for (int j = 0; j < 8; j++) sv[j] = sn[j];
    }

#pragma unroll
    for (int j = 0; j < 8; j++)
        *(float4*)&g_part_u[k][c][j * 128 + hoff] = acc[j];
    if (lane == 0) { g_part_m[k][c] = m; g_part_z[k][c] = z; }
}

// ---------------------------------------------------------------------------
// KMIX: blocks 0..255 combine the split-softmax partials into u[k][:]
//       (block 0 also computes the alpha==1 flag);
//       blocks 256..258 compute RH[l][:] = R_w[l] @ H_w (row-major vectorized).
// ---------------------------------------------------------------------------
__global__ __launch_bounds__(256) void kmix(
    const float* __restrict__ alpha, const float* __restrict__ Rw,
    const float* __restrict__ Hw)
{
    const int bid = blockIdx.x;
    const int t = threadIdx.x;

    if (bid < NB_) {
        const int k = bid;
        const int h4 = t * 4;

        if (k == 0) {
            int ok = 1;
#pragma unroll
            for (int r = 0; r < 4; r++) ok &= (alpha[h4 + r] == 1.0f);
            ok = __syncthreads_and(ok);
            if (t == 0) g_flag = ok;
        }

        float m = -3.0e38f;
#pragma unroll
        for (int c = 0; c < CHUNKS_; c++) m = fmaxf(m, g_part_m[k][c]);
        float Z = 0.f, w[CHUNKS_];
#pragma unroll
        for (int c = 0; c < CHUNKS_; c++) {
            w[c] = __expf(g_part_m[k][c] - m);
            Z += g_part_z[k][c] * w[c];
        }
        const float inv = 1.f / Z;
        float4 s = make_float4(0.f, 0.f, 0.f, 0.f);
#pragma unroll
        for (int c = 0; c < CHUNKS_; c++) {
            const float4 p = *(const float4*)&g_part_u[k][c][h4];
            const float ww = w[c] * inv;
            s.x += ww * p.x; s.y += ww * p.y; s.z += ww * p.z; s.w += ww * p.w;
        }
        *(float4*)&g_u[k][h4] = s;
    } else {
        // RH[l][j] = sum_h R[l,h] * H[h,j]; one block per l, thread owns 4 j's
        const int l = bid - NB_;
        const int j4 = t * 4;
        float4 s = make_float4(0.f, 0.f, 0.f, 0.f);
#pragma unroll 8
        for (int h = 0; h < HID_; h++) {
            const float r = __ldg(Rw + l * HID_ + h);
            const float4 hv = *(const float4*)(Hw + (size_t)h * HID_ + j4);
            s.x += r * hv.x; s.y += r * hv.y; s.z += r * hv.z; s.w += r * hv.w;
        }
        *(float4*)&g_RH[l][j4] = s;
    }
}

// ---------------------------------------------------------------------------
// Fast path (alpha == 1 so PReLU is identity):
//   out[i][l] = x[i]·R_w[l] + u[i]·RH[l]      (one warp per output, 768 warps)
// ---------------------------------------------------------------------------
__global__ __launch_bounds__(256) void k_fast(
    const float* __restrict__ ee, const float* __restrict__ Rw,
    float* __restrict__ out)
{
    if (!g_flag) return;
    const int w = (blockIdx.x * 256 + threadIdx.x) >> 5;
    if (w >= B_ * NL_) return;
    const int i = w / NL_;
    const int l = w % NL_;
    const int lane = threadIdx.x & 31;
    const float* xr = ee + (size_t)i * SEQ_ * HID_;
    float s = 0.f;
#pragma unroll
    for (int j0 = 0; j0 < HID_; j0 += 128) {
        const int j = j0 + lane * 4;
        const float4 xv = *(const float4*)(xr + j);
        const float4 rv = *(const float4*)(Rw + l * HID_ + j);
        const float4 uv = *(const float4*)&g_u[i][j];
        const float4 gv = *(const float4*)&g_RH[l][j];
        s += xv.x * rv.x + xv.y * rv.y + xv.z * rv.z + xv.w * rv.w
           + uv.x * gv.x + uv.y * gv.y + uv.z * gv.z + uv.w * gv.w;
    }
#pragma unroll
    for (int off = 16; off > 0; off >>= 1)
        s += __shfl_xor_sync(0xffffffffu, s, off);
    if (lane == 0) out[i * NL_ + l] = s;
}

// ---------------------------------------------------------------------------
// Slow path (general alpha): v = x + u@H^T, act = PReLU(v) -> g_act.
// Tiled 32x32 SGEMM-NT. Early-exits when flag==1.
// ---------------------------------------------------------------------------
__global__ __launch_bounds__(256) void k3_full(
    const float* __restrict__ ee, const float* __restrict__ Hw,
    const float* __restrict__ alpha)
{
    if (g_flag) return;
    __shared__ float Us[32][33];
    __shared__ float Hs[32][33];
    const int t  = threadIdx.x;
    const int tx = t & 15, ty = t >> 4;
    const int i0 = blockIdx.x * 32, h0 = blockIdx.y * 32;
    const int lr = t >> 3;           // 0..31
    const int lc = (t & 7) * 4;      // 0,4,..28
    float acc00 = 0.f, acc01 = 0.f, acc10 = 0.f, acc11 = 0.f;

    for (int kk = 0; kk < HID_; kk += 32) {
        const float4 uu = *(const float4*)&g_u[i0 + lr][kk + lc];
        const float4 hh = *(const float4*)(Hw + (size_t)(h0 + lr) * HID_ + kk + lc);
        Us[lr][lc] = uu.x; Us[lr][lc+1] = uu.y; Us[lr][lc+2] = uu.z; Us[lr][lc+3] = uu.w;
        Hs[lr][lc] = hh.x; Hs[lr][lc+1] = hh.y; Hs[lr][lc+2] = hh.z; Hs[lr][lc+3] = hh.w;
        __syncthreads();
#pragma unroll
        for (int j = 0; j < 32; j++) {
            const float a0 = Us[ty*2][j],   a1 = Us[ty*2+1][j];
            const float b0 = Hs[tx*2][j],   b1 = Hs[tx*2+1][j];
            acc00 += a0*b0; acc01 += a0*b1; acc10 += a1*b0; acc11 += a1*b1;
        }
        __syncthreads();
    }
    const float accs[2][2] = { {acc00, acc01}, {acc10, acc11} };
#pragma unroll
    for (int ii = 0; ii < 2; ii++)
#pragma unroll
        for (int jj = 0; jj < 2; jj++) {
            const int i = i0 + ty*2 + ii;
            const int h = h0 + tx*2 + jj;
            const float v = accs[ii][jj] + ee[(size_t)i * SEQ_ * HID_ + h];
            g_act[i][h] = (v >= 0.f) ? v : alpha[h] * v;
        }
}

// Slow path final: out = act @ R_w^T. One warp per output.
__global__ __launch_bounds__(256) void k4_full(
    const float* __restrict__ Rw, float* __restrict__ out)
{
    if (g_flag) return;
    const int w = (blockIdx.x * 256 + threadIdx.x) >> 5;
    if (w >= B_ * NL_) return;
    const int i = w / NL_;
    const int l = w % NL_;
    const int lane = threadIdx.x & 31;
    float s = 0.f;
#pragma unroll 8
    for (int j = lane; j < HID_; j += 32)
        s += g_act[i][j] * Rw[l * HID_ + j];
#pragma unroll
    for (int off = 16; off > 0; off >>= 1)
        s += __shfl_xor_sync(0xffffffffu, s, off);
    if (lane == 0) out[i * NL_ + l] = s;
}

// ---------------------------------------------------------------------------
extern "C" void kernel_launch(void* const* d_in, const int* in_sizes, int n_in,
                              void* d_out, int out_size)
{
    const float* ee = (const float*)d_in[0];   // (256,128,1024)
    const float* S  = (const float*)d_in[1];   // (256, 256*1024)
    const float* Hw = (const float*)d_in[2];   // (1024,1024)
    const float* Rw = (const float*)d_in[3];   // (3,1024)
    const float* al = (const float*)d_in[4];   // (1024,)
    float* out = (float*)d_out;                // (256,3)

    k1_partials<<<dim3(NB_ / KW_, CHUNKS_), 256>>>(ee, S);
    kmix<<<NB_ + NL_, 256>>>(al, Rw, Hw);
    k3_full<<<dim3(B_ / 32, HID_ / 32), 256>>>(ee, Hw, al);
    k4_full<<<(B_ * NL_ * 32) / 256, 256>>>(Rw, out);
    k_fast<<<(B_ * NL_ * 32) / 256, 256>>>(ee, Rw, out);
}